// round 1
// baseline (speedup 1.0000x reference)
#include <cuda_runtime.h>

// Rotated-BEV IoU loss.
// inputs: d_in[0] iou_pred (N,1) f32, d_in[1] box_pred (N,7) f32,
//         d_in[2] box_gt (M,7) f32, d_in[3] num_total_pos (scalar, int32 likely)
// output: d_out scalar f32

#define EPSF 1e-8f
#define MAXN 8192

__device__ float g_row[MAXN];   // per-pred-row |iou_pred - target| (unnormalized)

// Area of intersection of two convex quads (CCW), Sutherland-Hodgman clip of A by B.
__device__ __forceinline__ float quad_inter_area(
    const float* __restrict__ axs, const float* __restrict__ ays,
    const float* __restrict__ bxs, const float* __restrict__ bys)
{
    float px[8], py[8], qx[8], qy[8];
    int n = 4;
#pragma unroll
    for (int k = 0; k < 4; ++k) { px[k] = axs[k]; py[k] = ays[k]; }

#pragma unroll
    for (int e = 0; e < 4; ++e) {
        const float p1x = bxs[e], p1y = bys[e];
        const float ex = bxs[(e + 1) & 3] - p1x;
        const float ey = bys[(e + 1) & 3] - p1y;
        int m = 0;
        float xprev = px[n - 1], yprev = py[n - 1];
        float dprev = ex * (yprev - p1y) - ey * (xprev - p1x);
        for (int k = 0; k < n; ++k) {
            const float xc = px[k], yc = py[k];
            const float dc = ex * (yc - p1y) - ey * (xc - p1x);
            const bool inC = (dc >= 0.0f);
            const bool inP = (dprev >= 0.0f);
            if (inC != inP) {
                const float t = dprev / (dprev - dc);
                qx[m] = fmaf(t, xc - xprev, xprev);
                qy[m] = fmaf(t, yc - yprev, yprev);
                ++m;
            }
            if (inC) { qx[m] = xc; qy[m] = yc; ++m; }
            xprev = xc; yprev = yc; dprev = dc;
        }
        n = m;
        if (n == 0) return 0.0f;
        for (int k = 0; k < n; ++k) { px[k] = qx[k]; py[k] = qy[k]; }
    }
    if (n < 3) return 0.0f;

    float s = 0.0f;
    float xp = px[n - 1], yp = py[n - 1];
    for (int k = 0; k < n; ++k) {
        s += xp * py[k] - px[k] * yp;
        xp = px[k]; yp = py[k];
    }
    return 0.5f * fabsf(s);
}

__device__ __forceinline__ void box_corners(float x, float y, float dx, float dy,
                                            float yaw, float* cx, float* cy)
{
    float s, c;
    __sincosf(yaw, &s, &c);
    const float hx = 0.5f * dx, hy = 0.5f * dy;
    // local corners (hx,hy) (-hx,hy) (-hx,-hy) (hx,-hy)  -> CCW
    cx[0] = x + c * hx - s * hy;  cy[0] = y + s * hx + c * hy;
    cx[1] = x - c * hx - s * hy;  cy[1] = y - s * hx + c * hy;
    cx[2] = x - c * hx + s * hy;  cy[2] = y - s * hx - c * hy;
    cx[3] = x + c * hx + s * hy;  cy[3] = y + s * hx - c * hy;
}

__global__ void __launch_bounds__(256)
iou_row_kernel(const float* __restrict__ iou_pred,
               const float* __restrict__ box_pred,
               const float* __restrict__ box_gt,
               int N, int M)
{
    const int i = blockIdx.x;
    if (i >= N) return;

    const float* bp = box_pred + (size_t)i * 7;
    const float ax = bp[0], ay = bp[1], adx = bp[3], ady = bp[4], ayaw = bp[6];
    const float areaA = adx * ady;
    float axs[4], ays[4];
    box_corners(ax, ay, adx, ady, ayaw, axs, ays);

    float best = 0.0f;
    for (int j = threadIdx.x; j < M; j += blockDim.x) {
        const float* bg = box_gt + (size_t)j * 7;
        const float bx = bg[0], by = bg[1], bdx = bg[3], bdy = bg[4], byaw = bg[6];
        const float areaB = bdx * bdy;
        float bxs[4], bys[4];
        box_corners(bx, by, bdx, bdy, byaw, bxs, bys);

        const float inter = quad_inter_area(axs, ays, bxs, bys);
        const float uni = fmaxf(areaA + areaB - inter, EPSF);
        best = fmaxf(best, inter / uni);
    }

    __shared__ float red[256];
    red[threadIdx.x] = best;
    __syncthreads();
#pragma unroll
    for (int st = 128; st > 0; st >>= 1) {
        if (threadIdx.x < st)
            red[threadIdx.x] = fmaxf(red[threadIdx.x], red[threadIdx.x + st]);
        __syncthreads();
    }
    if (threadIdx.x == 0) {
        const float target = 2.0f * red[0] - 1.0f;
        g_row[i] = fabsf(iou_pred[i] - target);
    }
}

__global__ void __launch_bounds__(1024)
reduce_kernel(float* __restrict__ out, const int* __restrict__ ntp_ptr,
              int has_ntp, int N)
{
    __shared__ float red[1024];
    float s = 0.0f;
    for (int i = threadIdx.x; i < N; i += 1024) s += g_row[i];
    red[threadIdx.x] = s;
    __syncthreads();
#pragma unroll
    for (int st = 512; st > 0; st >>= 1) {
        if (threadIdx.x < st) red[threadIdx.x] += red[threadIdx.x + st];
        __syncthreads();
    }
    if (threadIdx.x == 0) {
        float ntp = 2048.0f;
        if (has_ntp) {
            const int iv = *ntp_ptr;
            // int32 scalar expected; if it looks like raw float bits, reinterpret.
            if (iv > 0 && iv < 100000000) ntp = (float)iv;
            else ntp = __int_as_float(iv);
        }
        out[0] = red[0] / (ntp + 1e-4f);
    }
}

extern "C" void kernel_launch(void* const* d_in, const int* in_sizes, int n_in,
                              void* d_out, int out_size)
{
    const float* iou_pred = (const float*)d_in[0];
    const float* box_pred = (const float*)d_in[1];
    const float* box_gt   = (const float*)d_in[2];
    const int N = in_sizes[1] / 7;
    const int M = in_sizes[2] / 7;
    const int* ntp_ptr = (n_in >= 4) ? (const int*)d_in[3] : nullptr;
    const int has_ntp = (n_in >= 4) ? 1 : 0;

    iou_row_kernel<<<N, 256>>>(iou_pred, box_pred, box_gt, N, M);
    reduce_kernel<<<1, 1024>>>((float*)d_out, ntp_ptr, has_ntp, N);
}

// round 2
// speedup vs baseline: 1.1070x; 1.1070x over previous
#include <cuda_runtime.h>

// Rotated-BEV IoU loss, compacted-survivor version.
// d_in[0] iou_pred (N,1) f32, d_in[1] box_pred (N,7) f32,
// d_in[2] box_gt (M,7) f32, d_in[3] num_total_pos (int32 scalar, optional)
// d_out: scalar f32

#define EPSF 1e-8f
#define MAXB 8192          // max total boxes (N + M)
#define ROWS_PER_BLOCK 8
#define BLOCK 256

// Precomputed per-box data: pred boxes at [0,N), gt boxes at [N, N+M)
__device__ float d_cx[MAXB];
__device__ float d_cy[MAXB];
__device__ float d_rad[MAXB];     // bounding-circle radius
__device__ float d_area[MAXB];
__device__ float d_crn[MAXB * 8]; // corners x0,y0,x1,y1,x2,y2,x3,y3 (CCW)

__device__ float g_row[MAXB];     // per-row |iou_pred - target|
__device__ int   g_counter = 0;   // last-block-done counter (self-resetting)

// ---------------------------------------------------------------------------
__global__ void __launch_bounds__(BLOCK)
prep_kernel(const float* __restrict__ box_pred,
            const float* __restrict__ box_gt, int N, int M)
{
    const int i = blockIdx.x * BLOCK + threadIdx.x;
    if (i >= N + M) return;
    const float* b = (i < N) ? (box_pred + (size_t)i * 7)
                             : (box_gt + (size_t)(i - N) * 7);
    const float x = b[0], y = b[1], dx = b[3], dy = b[4], yaw = b[6];
    float s, c;
    __sincosf(yaw, &s, &c);
    const float hx = 0.5f * dx, hy = 0.5f * dy;
    float* cr = d_crn + (size_t)i * 8;
    // CCW: (hx,hy) (-hx,hy) (-hx,-hy) (hx,-hy)
    cr[0] = x + c * hx - s * hy;  cr[1] = y + s * hx + c * hy;
    cr[2] = x - c * hx - s * hy;  cr[3] = y - s * hx + c * hy;
    cr[4] = x - c * hx + s * hy;  cr[5] = y - s * hx - c * hy;
    cr[6] = x + c * hx + s * hy;  cr[7] = y + s * hx - c * hy;
    d_cx[i] = x; d_cy[i] = y;
    d_rad[i] = sqrtf(hx * hx + hy * hy) + 1e-4f;
    d_area[i] = dx * dy;
}

// ---------------------------------------------------------------------------
// Intersection area of two convex CCW quads (8 floats each, x0,y0,...).
__device__ float quad_inter_area(const float* __restrict__ A, const float* B)
{
    float px[8], py[8], qx[8], qy[8];
    int n = 4;
#pragma unroll
    for (int k = 0; k < 4; ++k) { px[k] = A[2 * k]; py[k] = A[2 * k + 1]; }

#pragma unroll
    for (int e = 0; e < 4; ++e) {
        const float p1x = B[2 * e], p1y = B[2 * e + 1];
        const int e2 = ((e + 1) & 3) * 2;
        const float ex = B[e2] - p1x, ey = B[e2 + 1] - p1y;
        int m = 0;
        float xprev = px[n - 1], yprev = py[n - 1];
        float dprev = ex * (yprev - p1y) - ey * (xprev - p1x);
        for (int k = 0; k < n; ++k) {
            const float xc = px[k], yc = py[k];
            const float dc = ex * (yc - p1y) - ey * (xc - p1x);
            if ((dc >= 0.0f) != (dprev >= 0.0f)) {
                const float t = dprev / (dprev - dc);
                qx[m] = fmaf(t, xc - xprev, xprev);
                qy[m] = fmaf(t, yc - yprev, yprev);
                ++m;
            }
            if (dc >= 0.0f) { qx[m] = xc; qy[m] = yc; ++m; }
            xprev = xc; yprev = yc; dprev = dc;
        }
        n = m;
        if (n == 0) return 0.0f;
        for (int k = 0; k < n; ++k) { px[k] = qx[k]; py[k] = qy[k]; }
    }
    if (n < 3) return 0.0f;
    float s = 0.0f;
    float xp = px[n - 1], yp = py[n - 1];
    for (int k = 0; k < n; ++k) {
        s += xp * py[k] - px[k] * yp;
        xp = px[k]; yp = py[k];
    }
    return 0.5f * fabsf(s);
}

// ---------------------------------------------------------------------------
// dynamic smem layout: scx[M], scy[M], srad[M], sarea[M] floats, slist[M] ints
__global__ void __launch_bounds__(BLOCK)
iou_main_kernel(const float* __restrict__ iou_pred,
                float* __restrict__ out,
                const int* __restrict__ ntp_ptr, int has_ntp,
                int N, int M)
{
    extern __shared__ float sm[];
    float* scx = sm;
    float* scy = scx + M;
    float* srad = scy + M;
    float* sarea = srad + M;
    int* slist = (int*)(sarea + M);

    __shared__ int   scnt;
    __shared__ int   smaxbits;
    __shared__ float red[BLOCK];
    __shared__ int   isLast;

    const int tid = threadIdx.x;

    // stage gt data (gt boxes live at global index N + j)
    for (int j = tid; j < M; j += BLOCK) {
        scx[j] = d_cx[N + j];
        scy[j] = d_cy[N + j];
        srad[j] = d_rad[N + j];
        sarea[j] = d_area[N + j];
    }

    const int row0 = blockIdx.x * ROWS_PER_BLOCK;
#pragma unroll 1
    for (int r = 0; r < ROWS_PER_BLOCK; ++r) {
        const int row = row0 + r;
        if (row >= N) break;
        if (tid == 0) { scnt = 0; smaxbits = 0; }
        __syncthreads();

        const float pcx = d_cx[row], pcy = d_cy[row], prad = d_rad[row];
        // phase 1: circle rejection + compaction
        for (int j = tid; j < M; j += BLOCK) {
            const float ddx = pcx - scx[j];
            const float ddy = pcy - scy[j];
            const float rr = prad + srad[j];
            if (ddx * ddx + ddy * ddy <= rr * rr) {
                const int idx = atomicAdd(&scnt, 1);
                slist[idx] = j;
            }
        }
        __syncthreads();

        // phase 2: clip survivors only
        const int cnt = scnt;
        if (tid < cnt) {
            const int j = slist[tid];
            float B[8];
            const float* bg = d_crn + (size_t)(N + j) * 8;
#pragma unroll
            for (int k = 0; k < 8; ++k) B[k] = bg[k];
            const float inter = quad_inter_area(d_crn + (size_t)row * 8, B);
            const float areaA = d_area[row];
            const float uni = fmaxf(areaA + sarea[j] - inter, EPSF);
            const float iou = inter / uni;   // >= 0
            atomicMax(&smaxbits, __float_as_int(iou));
        }
        __syncthreads();

        if (tid == 0) {
            const float mx = __int_as_float(smaxbits);
            g_row[row] = fabsf(iou_pred[row] - (2.0f * mx - 1.0f));
        }
        __syncthreads();
    }

    // fused final reduction: last block to finish sums g_row
    if (tid == 0) {
        __threadfence();
        const int prev = atomicAdd(&g_counter, 1);
        isLast = (prev == (int)gridDim.x - 1);
    }
    __syncthreads();
    if (!isLast) return;
    __threadfence();

    float s = 0.0f;
    for (int i = tid; i < N; i += BLOCK) s += g_row[i];
    red[tid] = s;
    __syncthreads();
#pragma unroll
    for (int st = BLOCK / 2; st > 0; st >>= 1) {
        if (tid < st) red[tid] += red[tid + st];
        __syncthreads();
    }
    if (tid == 0) {
        float ntp = 2048.0f;
        if (has_ntp) {
            const int iv = *ntp_ptr;
            if (iv > 0 && iv < 100000000) ntp = (float)iv;
            else ntp = __int_as_float(iv);
        }
        out[0] = red[0] / (ntp + 1e-4f);
        g_counter = 0;   // reset for next graph replay
    }
}

// ---------------------------------------------------------------------------
extern "C" void kernel_launch(void* const* d_in, const int* in_sizes, int n_in,
                              void* d_out, int out_size)
{
    const float* iou_pred = (const float*)d_in[0];
    const float* box_pred = (const float*)d_in[1];
    const float* box_gt   = (const float*)d_in[2];
    const int N = in_sizes[1] / 7;
    const int M = in_sizes[2] / 7;
    const int* ntp_ptr = (n_in >= 4) ? (const int*)d_in[3] : nullptr;
    const int has_ntp = (n_in >= 4) ? 1 : 0;

    const int total = N + M;
    prep_kernel<<<(total + BLOCK - 1) / BLOCK, BLOCK>>>(box_pred, box_gt, N, M);

    const int grid = (N + ROWS_PER_BLOCK - 1) / ROWS_PER_BLOCK;
    const size_t smem = (size_t)M * 4 * sizeof(float) + (size_t)M * sizeof(int);
    iou_main_kernel<<<grid, BLOCK, smem>>>(iou_pred, (float*)d_out,
                                           ntp_ptr, has_ntp, N, M);
}

// round 3
// speedup vs baseline: 1.7011x; 1.5366x over previous
#include <cuda_runtime.h>

// Rotated-BEV IoU loss — flat pair-test -> global survivor list -> parallel clip.
// d_in[0] iou_pred (N,1) f32, d_in[1] box_pred (N,7) f32,
// d_in[2] box_gt (M,7) f32, d_in[3] num_total_pos (int32 scalar, optional)
// d_out: scalar f32

#define EPSF 1e-8f
#define MAXN 8192
#define PAIR_CAP 131072
#define TBLOCK 256
#define CBLOCK 128
#define CGRID  256

__device__ int   g_rowmax[MAXN];      // float-bits of per-row max IoU (>=0)
__device__ int   g_pairs[PAIR_CAP];   // packed (row<<16)|j
__device__ int   g_paircnt = 0;

// ---------------------------------------------------------------------------
__device__ __forceinline__ void box_corners_raw(const float* __restrict__ b,
                                                float* __restrict__ C)
{
    const float x = b[0], y = b[1];
    const float hx = 0.5f * b[3], hy = 0.5f * b[4];
    float s, c;
    __sincosf(b[6], &s, &c);
    // CCW: (hx,hy) (-hx,hy) (-hx,-hy) (hx,-hy)
    C[0] = x + c * hx - s * hy;  C[1] = y + s * hx + c * hy;
    C[2] = x - c * hx - s * hy;  C[3] = y - s * hx + c * hy;
    C[4] = x - c * hx + s * hy;  C[5] = y - s * hx - c * hy;
    C[6] = x + c * hx + s * hy;  C[7] = y + s * hx - c * hy;
}

// Intersection area of two convex CCW quads (x0,y0,...,x3,y3).
__device__ float quad_inter_area(const float* __restrict__ A,
                                 const float* __restrict__ B)
{
    float px[8], py[8], qx[8], qy[8];
    int n = 4;
#pragma unroll
    for (int k = 0; k < 4; ++k) { px[k] = A[2 * k]; py[k] = A[2 * k + 1]; }

#pragma unroll
    for (int e = 0; e < 4; ++e) {
        const float p1x = B[2 * e], p1y = B[2 * e + 1];
        const int e2 = ((e + 1) & 3) * 2;
        const float ex = B[e2] - p1x, ey = B[e2 + 1] - p1y;
        int m = 0;
        float xprev = px[n - 1], yprev = py[n - 1];
        float dprev = ex * (yprev - p1y) - ey * (xprev - p1x);
        for (int k = 0; k < n; ++k) {
            const float xc = px[k], yc = py[k];
            const float dc = ex * (yc - p1y) - ey * (xc - p1x);
            if ((dc >= 0.0f) != (dprev >= 0.0f)) {
                const float t = dprev / (dprev - dc);
                qx[m] = fmaf(t, xc - xprev, xprev);
                qy[m] = fmaf(t, yc - yprev, yprev);
                ++m;
            }
            if (dc >= 0.0f) { qx[m] = xc; qy[m] = yc; ++m; }
            xprev = xc; yprev = yc; dprev = dc;
        }
        n = m;
        if (n == 0) return 0.0f;
        for (int k = 0; k < n; ++k) { px[k] = qx[k]; py[k] = qy[k]; }
    }
    if (n < 3) return 0.0f;
    float s = 0.0f;
    float xp = px[n - 1], yp = py[n - 1];
    for (int k = 0; k < n; ++k) {
        s += xp * py[k] - px[k] * yp;
        xp = px[k]; yp = py[k];
    }
    return 0.5f * fabsf(s);
}

// ---------------------------------------------------------------------------
// Pair-test kernel: each block covers ROWS_PB pred rows x all M gt boxes.
// smem: gt centers + radii; survivors -> global list.
#define ROWS_PB 16
__global__ void __launch_bounds__(TBLOCK)
pair_test_kernel(const float* __restrict__ box_pred,
                 const float* __restrict__ box_gt, int N, int M)
{
    extern __shared__ float sm[];
    float* gx = sm;            // M
    float* gy = gx + M;        // M
    float* gr = gy + M;        // M

    const int tid = threadIdx.x;

    for (int j = tid; j < M; j += TBLOCK) {
        const float* b = box_gt + (size_t)j * 7;
        const float hx = 0.5f * b[3], hy = 0.5f * b[4];
        gx[j] = b[0]; gy[j] = b[1];
        gr[j] = sqrtf(hx * hx + hy * hy);
    }

    __shared__ float px_[ROWS_PB], py_[ROWS_PB], pr_[ROWS_PB];
    const int row0 = blockIdx.x * ROWS_PB;
    if (tid < ROWS_PB) {
        const int row = row0 + tid;
        if (row < N) {
            const float* b = box_pred + (size_t)row * 7;
            const float hx = 0.5f * b[3], hy = 0.5f * b[4];
            px_[tid] = b[0]; py_[tid] = b[1];
            pr_[tid] = sqrtf(hx * hx + hy * hy);
            g_rowmax[row] = 0;   // re-init every replay
        }
    }
    __syncthreads();

    const int npairs = ROWS_PB * M;
    for (int p = tid; p < npairs; p += TBLOCK) {
        const int r = p / M;
        const int j = p - r * M;
        const int row = row0 + r;
        if (row >= N) break;
        const float ddx = px_[r] - gx[j];
        const float ddy = py_[r] - gy[j];
        const float rr = pr_[r] + gr[j] + 1e-4f;
        if (ddx * ddx + ddy * ddy <= rr * rr) {
            const int idx = atomicAdd(&g_paircnt, 1);
            if (idx < PAIR_CAP) g_pairs[idx] = (row << 16) | j;
        }
    }
}

// ---------------------------------------------------------------------------
// Clip kernel: one thread per surviving pair (grid-stride over device count).
__global__ void __launch_bounds__(CBLOCK)
clip_kernel(const float* __restrict__ box_pred,
            const float* __restrict__ box_gt)
{
    const int cnt = min(g_paircnt, PAIR_CAP);
    const int stride = gridDim.x * CBLOCK;
    for (int i = blockIdx.x * CBLOCK + threadIdx.x; i < cnt; i += stride) {
        const int packed = g_pairs[i];
        const int row = packed >> 16;
        const int j = packed & 0xFFFF;
        const float* bp = box_pred + (size_t)row * 7;
        const float* bg = box_gt + (size_t)j * 7;
        float A[8], B[8];
        box_corners_raw(bp, A);
        box_corners_raw(bg, B);
        const float inter = quad_inter_area(A, B);
        if (inter > 0.0f) {
            const float uni = fmaxf(bp[3] * bp[4] + bg[3] * bg[4] - inter, EPSF);
            const float iou = inter / uni;
            atomicMax(&g_rowmax[row], __float_as_int(iou));
        }
    }
}

// ---------------------------------------------------------------------------
__global__ void __launch_bounds__(1024)
final_kernel(const float* __restrict__ iou_pred, float* __restrict__ out,
             const int* __restrict__ ntp_ptr, int has_ntp, int N)
{
    __shared__ float red[1024];
    float s = 0.0f;
    for (int i = threadIdx.x; i < N; i += 1024) {
        const float mx = __int_as_float(g_rowmax[i]);
        s += fabsf(iou_pred[i] - (2.0f * mx - 1.0f));
    }
    red[threadIdx.x] = s;
    __syncthreads();
#pragma unroll
    for (int st = 512; st > 0; st >>= 1) {
        if (threadIdx.x < st) red[threadIdx.x] += red[threadIdx.x + st];
        __syncthreads();
    }
    if (threadIdx.x == 0) {
        float ntp = 2048.0f;
        if (has_ntp) {
            const int iv = *ntp_ptr;
            if (iv > 0 && iv < 100000000) ntp = (float)iv;
            else ntp = __int_as_float(iv);
        }
        out[0] = red[0] / (ntp + 1e-4f);
        g_paircnt = 0;   // reset for next graph replay
    }
}

// ---------------------------------------------------------------------------
extern "C" void kernel_launch(void* const* d_in, const int* in_sizes, int n_in,
                              void* d_out, int out_size)
{
    const float* iou_pred = (const float*)d_in[0];
    const float* box_pred = (const float*)d_in[1];
    const float* box_gt   = (const float*)d_in[2];
    const int N = in_sizes[1] / 7;
    const int M = in_sizes[2] / 7;
    const int* ntp_ptr = (n_in >= 4) ? (const int*)d_in[3] : nullptr;
    const int has_ntp = (n_in >= 4) ? 1 : 0;

    const int grid = (N + ROWS_PB - 1) / ROWS_PB;
    const size_t smem = (size_t)M * 3 * sizeof(float);
    pair_test_kernel<<<grid, TBLOCK, smem>>>(box_pred, box_gt, N, M);
    clip_kernel<<<CGRID, CBLOCK>>>(box_pred, box_gt);
    final_kernel<<<1, 1024>>>(iou_pred, (float*)d_out, ntp_ptr, has_ntp, N);
}

// round 4
// speedup vs baseline: 1.9958x; 1.1732x over previous
#include <cuda_runtime.h>

// Rotated-BEV IoU loss — prep -> flat AABB test (warp-aggregated push) ->
// clip + fused last-block reduction.
// d_in[0] iou_pred (N,1) f32, d_in[1] box_pred (N,7) f32,
// d_in[2] box_gt (M,7) f32, d_in[3] num_total_pos (int32 scalar, optional)
// d_out: scalar f32

#define EPSF 1e-8f
#define MAXB 8192
#define PAIR_CAP 131072
#define PBLOCK 256
#define TBLOCK 256
#define TGRID  1024
#define CBLOCK 256
#define CGRID  48

__device__ float d_cx[MAXB], d_cy[MAXB];     // centers
__device__ float d_ex[MAXB], d_ey[MAXB];     // AABB half-extents
__device__ float d_area[MAXB];
__device__ float d_crn[MAXB * 8];            // corners x0,y0,...,x3,y3 CCW

__device__ int g_rowmax[MAXB];               // float bits of row max IoU (>=0)
__device__ int g_pairs[PAIR_CAP];            // packed (row<<16)|j
__device__ int g_paircnt = 0;
__device__ int g_done = 0;

// ---------------------------------------------------------------------------
__global__ void __launch_bounds__(PBLOCK)
prep_kernel(const float* __restrict__ box_pred,
            const float* __restrict__ box_gt, int N, int M)
{
    const int i = blockIdx.x * PBLOCK + threadIdx.x;
    if (i < N) g_rowmax[i] = 0;
    if (i >= N + M) return;
    const float* b = (i < N) ? (box_pred + (size_t)i * 7)
                             : (box_gt + (size_t)(i - N) * 7);
    const float x = b[0], y = b[1], dx = b[3], dy = b[4], yaw = b[6];
    float s, c;
    __sincosf(yaw, &s, &c);
    const float hx = 0.5f * dx, hy = 0.5f * dy;
    float* cr = d_crn + (size_t)i * 8;
    cr[0] = x + c * hx - s * hy;  cr[1] = y + s * hx + c * hy;
    cr[2] = x - c * hx - s * hy;  cr[3] = y - s * hx + c * hy;
    cr[4] = x - c * hx + s * hy;  cr[5] = y - s * hx - c * hy;
    cr[6] = x + c * hx + s * hy;  cr[7] = y + s * hx - c * hy;
    d_cx[i] = x; d_cy[i] = y;
    const float ac = fabsf(c), as = fabsf(s);
    d_ex[i] = hx * ac + hy * as + 1e-4f;
    d_ey[i] = hx * as + hy * ac + 1e-4f;
    d_area[i] = dx * dy;
}

// ---------------------------------------------------------------------------
// Flat AABB test over all N*M pairs; warp-aggregated survivor push.
__global__ void __launch_bounds__(TBLOCK)
pair_test_kernel(int N, int M)
{
    const int total = N * M;
    const int stride = gridDim.x * TBLOCK;
    const int lane = threadIdx.x & 31;

    for (int p = blockIdx.x * TBLOCK + threadIdx.x; p < total; p += stride) {
        const int row = p / M;
        const int j = p - row * M;
        const int gj = N + j;
        const float ddx = fabsf(d_cx[row] - d_cx[gj]);
        const float ddy = fabsf(d_cy[row] - d_cy[gj]);
        const bool pass = (ddx <= d_ex[row] + d_ex[gj]) &
                          (ddy <= d_ey[row] + d_ey[gj]);

        const unsigned m = __ballot_sync(0xFFFFFFFFu, pass);
        if (m) {
            const int leader = __ffs(m) - 1;
            int base = 0;
            if (lane == leader) base = atomicAdd(&g_paircnt, __popc(m));
            base = __shfl_sync(0xFFFFFFFFu, base, leader);
            if (pass) {
                const int idx = base + __popc(m & ((1u << lane) - 1u));
                if (idx < PAIR_CAP) g_pairs[idx] = (row << 16) | j;
            }
        }
    }
}

// ---------------------------------------------------------------------------
// Intersection area of two convex CCW quads (x0,y0,...,x3,y3).
__device__ float quad_inter_area(const float* __restrict__ A,
                                 const float* __restrict__ B)
{
    float px[8], py[8], qx[8], qy[8];
    int n = 4;
#pragma unroll
    for (int k = 0; k < 4; ++k) { px[k] = A[2 * k]; py[k] = A[2 * k + 1]; }

#pragma unroll
    for (int e = 0; e < 4; ++e) {
        const float p1x = B[2 * e], p1y = B[2 * e + 1];
        const int e2 = ((e + 1) & 3) * 2;
        const float ex = B[e2] - p1x, ey = B[e2 + 1] - p1y;
        int m = 0;
        float xprev = px[n - 1], yprev = py[n - 1];
        float dprev = ex * (yprev - p1y) - ey * (xprev - p1x);
        for (int k = 0; k < n; ++k) {
            const float xc = px[k], yc = py[k];
            const float dc = ex * (yc - p1y) - ey * (xc - p1x);
            if ((dc >= 0.0f) != (dprev >= 0.0f)) {
                const float t = dprev / (dprev - dc);
                qx[m] = fmaf(t, xc - xprev, xprev);
                qy[m] = fmaf(t, yc - yprev, yprev);
                ++m;
            }
            if (dc >= 0.0f) { qx[m] = xc; qy[m] = yc; ++m; }
            xprev = xc; yprev = yc; dprev = dc;
        }
        n = m;
        if (n == 0) return 0.0f;
        for (int k = 0; k < n; ++k) { px[k] = qx[k]; py[k] = qy[k]; }
    }
    if (n < 3) return 0.0f;
    float s = 0.0f;
    float xp = px[n - 1], yp = py[n - 1];
    for (int k = 0; k < n; ++k) {
        s += xp * py[k] - px[k] * yp;
        xp = px[k]; yp = py[k];
    }
    return 0.5f * fabsf(s);
}

// ---------------------------------------------------------------------------
// Clip survivors (dense, all lanes busy) + last-block final reduction.
__global__ void __launch_bounds__(CBLOCK)
clip_kernel(const float* __restrict__ iou_pred, float* __restrict__ out,
            const int* __restrict__ ntp_ptr, int has_ntp, int N)
{
    const int cnt = min(g_paircnt, PAIR_CAP);
    const int stride = gridDim.x * CBLOCK;
    const int tid = threadIdx.x;

    for (int i = blockIdx.x * CBLOCK + tid; i < cnt; i += stride) {
        const int packed = g_pairs[i];
        const int row = packed >> 16;
        const int j = packed & 0xFFFF;
        float A[8], B[8];
        const float4* pa = (const float4*)(d_crn + (size_t)row * 8);
        const float4* pb = (const float4*)(d_crn + (size_t)(N + j) * 8);
        float4 a0 = pa[0], a1 = pa[1], b0 = pb[0], b1 = pb[1];
        A[0] = a0.x; A[1] = a0.y; A[2] = a0.z; A[3] = a0.w;
        A[4] = a1.x; A[5] = a1.y; A[6] = a1.z; A[7] = a1.w;
        B[0] = b0.x; B[1] = b0.y; B[2] = b0.z; B[3] = b0.w;
        B[4] = b1.x; B[5] = b1.y; B[6] = b1.z; B[7] = b1.w;
        const float inter = quad_inter_area(A, B);
        if (inter > 0.0f) {
            const float uni = fmaxf(d_area[row] + d_area[N + j] - inter, EPSF);
            atomicMax(&g_rowmax[row], __float_as_int(inter / uni));
        }
    }

    // -------- last block does the deterministic final reduction --------
    __shared__ int isLast;
    if (tid == 0) {
        __threadfence();
        isLast = (atomicAdd(&g_done, 1) == (int)gridDim.x - 1);
    }
    __syncthreads();
    if (!isLast) return;
    __threadfence();

    float s = 0.0f;
    for (int i = tid; i < N; i += CBLOCK) {
        const float mx = __int_as_float(g_rowmax[i]);
        s += fabsf(iou_pred[i] - (2.0f * mx - 1.0f));
    }
#pragma unroll
    for (int o = 16; o > 0; o >>= 1)
        s += __shfl_down_sync(0xFFFFFFFFu, s, o);

    __shared__ float wsum[CBLOCK / 32];
    if ((tid & 31) == 0) wsum[tid >> 5] = s;
    __syncthreads();
    if (tid == 0) {
        float tot = 0.0f;
#pragma unroll
        for (int w = 0; w < CBLOCK / 32; ++w) tot += wsum[w];
        float ntp = 2048.0f;
        if (has_ntp) {
            const int iv = *ntp_ptr;
            if (iv > 0 && iv < 100000000) ntp = (float)iv;
            else ntp = __int_as_float(iv);
        }
        out[0] = tot / (ntp + 1e-4f);
        g_paircnt = 0;      // reset for next replay
        g_done = 0;
    }
}

// ---------------------------------------------------------------------------
extern "C" void kernel_launch(void* const* d_in, const int* in_sizes, int n_in,
                              void* d_out, int out_size)
{
    const float* iou_pred = (const float*)d_in[0];
    const float* box_pred = (const float*)d_in[1];
    const float* box_gt   = (const float*)d_in[2];
    const int N = in_sizes[1] / 7;
    const int M = in_sizes[2] / 7;
    const int* ntp_ptr = (n_in >= 4) ? (const int*)d_in[3] : nullptr;
    const int has_ntp = (n_in >= 4) ? 1 : 0;

    prep_kernel<<<(N + M + PBLOCK - 1) / PBLOCK, PBLOCK>>>(box_pred, box_gt, N, M);
    pair_test_kernel<<<TGRID, TBLOCK>>>(N, M);
    clip_kernel<<<CGRID, CBLOCK>>>(iou_pred, (float*)d_out, ntp_ptr, has_ntp, N);
}